// round 6
// baseline (speedup 1.0000x reference)
#include <cuda_runtime.h>
#include <cuda_bf16.h>
#include <math.h>

#define BB 32
#define TT 2048
#define FF 512
#define HH 512
#define G4 (4*HH)
#define NCTA 128

typedef unsigned long long u64;

// ---------------- scratch ----------------
__device__ float g_xg[(size_t)TT * BB * G4];   // [T][B][4H]
__device__ float g_hbuf[2][BB * HH];           // ping-pong h
__device__ int g_bar[TT];

// ---------------- packed f32x2 + fast-math helpers ----------------
__device__ __forceinline__ u64 f2dup(float v) {
    u64 r; asm("mov.b64 %0, {%1, %1};" : "=l"(r) : "f"(v)); return r;
}
__device__ __forceinline__ u64 f2pack(float lo, float hi) {
    u64 r; asm("mov.b64 %0, {%1, %2};" : "=l"(r) : "f"(lo), "f"(hi)); return r;
}
__device__ __forceinline__ u64 fma2(u64 a, u64 b, u64 c) {
    u64 d; asm("fma.rn.f32x2 %0, %1, %2, %3;" : "=l"(d) : "l"(a), "l"(b), "l"(c)); return d;
}
__device__ __forceinline__ u64 add2(u64 a, u64 b) {
    u64 d; asm("add.rn.f32x2 %0, %1, %2;" : "=l"(d) : "l"(a), "l"(b)); return d;
}
__device__ __forceinline__ float2 unpack2(u64 v) {
    float2 r; asm("mov.b64 {%0, %1}, %2;" : "=f"(r.x), "=f"(r.y) : "l"(v)); return r;
}
__device__ __forceinline__ float fex2(float x) {
    float r; asm("ex2.approx.f32 %0, %1;" : "=f"(r) : "f"(x)); return r;
}
__device__ __forceinline__ float frcp(float x) {
    float r; asm("rcp.approx.f32 %0, %1;" : "=f"(r) : "f"(x)); return r;
}
#define LOG2E 1.4426950408889634f
__device__ __forceinline__ float fsig(float x) { return frcp(1.f + fex2(-LOG2E * x)); }
__device__ __forceinline__ float ftanh(float x) { return 2.f * frcp(1.f + fex2(-2.f * LOG2E * x)) - 1.f; }

// ---------------- GEMM: Xg = x @ Wi + bias (double-buffered, FFMA2) ----------------
__global__ __launch_bounds__(256) void gemm_xwi(
    const float* __restrict__ x, const float* __restrict__ Wi,
    const float* __restrict__ bias)
{
    __shared__ u64   asd[2][8][128];
    __shared__ float bsd[2][8][128];

    const int tid = threadIdx.x;
    if (blockIdx.y == 0 && blockIdx.x < 8) {
        g_bar[blockIdx.x * 256 + tid] = 0;   // replay-safe barrier re-init
    }

    const int tx = tid & 15;
    const int ty = tid >> 4;
    const int row0 = blockIdx.y * 128;
    const int col0 = blockIdx.x * 128;

    const int ar = tid >> 1, ac = tid & 1;
    const int br = tid >> 5, bc = tid & 31;

    const float* aptr = x + (size_t)(row0 + ar) * FF + ac * 4;
    const float* bptr = Wi + (size_t)br * G4 + col0 + bc * 4;

    float4 av = *(const float4*)aptr;
    float4 bv = *(const float4*)bptr;

    u64 acc[8][4];
#pragma unroll
    for (int i = 0; i < 8; i++)
#pragma unroll
        for (int j = 0; j < 4; j++) acc[i][j] = 0ull;

    int p = 0;
    for (int s = 0; s < 64; s++) {
        asd[p][ac * 4 + 0][ar] = f2dup(av.x);
        asd[p][ac * 4 + 1][ar] = f2dup(av.y);
        asd[p][ac * 4 + 2][ar] = f2dup(av.z);
        asd[p][ac * 4 + 3][ar] = f2dup(av.w);
        *(float4*)&bsd[p][br][bc * 4] = bv;
        __syncthreads();
        if (s < 63) {
            av = *(const float4*)(aptr + (s + 1) * 8);
            bv = *(const float4*)(bptr + (size_t)(s + 1) * 8 * G4);
        }
#pragma unroll
        for (int kk = 0; kk < 8; kk++) {
            const ulonglong2* ap2 = (const ulonglong2*)&asd[p][kk][ty * 8];
            ulonglong2 q0 = ap2[0], q1 = ap2[1], q2 = ap2[2], q3 = ap2[3];
            const ulonglong2* bp2 = (const ulonglong2*)&bsd[p][kk][tx * 8];
            ulonglong2 r0 = bp2[0], r1 = bp2[1];
            u64 aa[8] = {q0.x, q0.y, q1.x, q1.y, q2.x, q2.y, q3.x, q3.y};
            u64 bb2[4] = {r0.x, r0.y, r1.x, r1.y};
#pragma unroll
            for (int i = 0; i < 8; i++)
#pragma unroll
                for (int j = 0; j < 4; j++)
                    acc[i][j] = fma2(aa[i], bb2[j], acc[i][j]);
        }
        __syncthreads();
        p ^= 1;
    }

    const int cbase = col0 + tx * 8;
    float4 bia0 = *(const float4*)(bias + cbase);
    float4 bia1 = *(const float4*)(bias + cbase + 4);
#pragma unroll
    for (int i = 0; i < 8; i++) {
        int r = row0 + ty * 8 + i;
        int bidx = r >> 11;
        int t = r & (TT - 1);
        float* dst = g_xg + (size_t)t * (BB * G4) + (size_t)bidx * G4 + cbase;
        float2 p0 = unpack2(acc[i][0]);
        float2 p1 = unpack2(acc[i][1]);
        float2 p2 = unpack2(acc[i][2]);
        float2 p3 = unpack2(acc[i][3]);
        float4 v0, v1;
        v0.x = p0.x + bia0.x; v0.y = p0.y + bia0.y;
        v0.z = p1.x + bia0.z; v0.w = p1.y + bia0.w;
        v1.x = p2.x + bia1.x; v1.y = p2.y + bia1.y;
        v1.z = p3.x + bia1.z; v1.w = p3.y + bia1.w;
        *(float4*)(dst) = v0;
        *(float4*)(dst + 4) = v1;
    }
}

// ---------------- persistent recurrent kernel: Wh in REGISTERS ----------------
// 128 CTAs x 256 threads. CTA owns j0..j0+3 (16 gate-cols).
// Thread = (c = tid&15 [col: g=c>>2, jj=c&3], kc = 3-bit k-chunk of 64,
//           bh = tid>>7 [16 b's]).  wreg[32] u64 = this thread's Wh slice
//           (k-pairs), loaded once.  Per step only h flows through SMEM.
// hs4f layout: [b][kc][m4] float4, row 136 f4 (8 chunks x 17) -> both the
// stage stores and the dot loads are bank-conflict-free; dot loads are
// 16-lane broadcasts (warp = 16 c x 2 kc).
// part layout: row p = b*16+c, 10 u64/row (16B-aligned rows), col kc.
#define HS_F4     (32 * 136)                 // 4352 float4 = 69632 B
#define PART_U64  (512 * 10)                 // 40960 B
#define SMEM_REC_BYTES (HS_F4 * 16 + PART_U64 * 8)

__global__ __launch_bounds__(256, 1) void lstm_rec(
    const float* __restrict__ Wh,
    const float* __restrict__ c0, const float* __restrict__ h0,
    float* __restrict__ out)
{
    extern __shared__ char smraw[];
    float4* hs4f = (float4*)smraw;                       // [32][136]
    u64*    part = (u64*)(smraw + HS_F4 * 16);           // [512][10]

    const int tid = threadIdx.x;
    const int cta = blockIdx.x;
    const int j0 = cta * 4;

    const int c   = tid & 15;
    const int kc  = ((tid >> 4) & 1) | (((tid >> 5) & 3) << 1);
    const int bh  = tid >> 7;
    const int wcol = (c >> 2) * HH + j0 + (c & 3);

    // one-time Wh slice -> registers (64 strided LDGs)
    u64 wreg[32];
    {
        const float* wp = Wh + (size_t)(kc * 64) * G4 + wcol;
#pragma unroll
        for (int m = 0; m < 32; m++) {
            float lo = __ldg(wp + (size_t)(2 * m) * G4);
            float hi = __ldg(wp + (size_t)(2 * m + 1) * G4);
            wreg[m] = f2pack(lo, hi);
        }
    }

    // reducer mapping (tid < 128): (b, jj)
    const int b_r = tid >> 2;
    const int jj_r = tid & 3;
    const int j_r = j0 + jj_r;

    float creg = 0.f;
    if (tid < 128) creg = c0[b_r * HH + j_r];

    float* outc = out;
    float* outh = out + BB * HH;
    float* ys   = out + 2 * BB * HH;

    for (int t = 0; t < TT; t++) {
        // ---- stage h: coalesced gmem read, conflict-free smem store ----
        const float4* hsrc = (t == 0) ? (const float4*)h0 : (const float4*)g_hbuf[t & 1];
#pragma unroll
        for (int m = 0; m < 16; m++) {
            int f4 = tid + m * 256;          // b*128 + k4
            int bb = f4 >> 7;
            int k4 = f4 & 127;
            hs4f[bb * 136 + (k4 >> 4) * 17 + (k4 & 15)] = __ldcv(hsrc + f4);
        }
        // xg prefetch (hides under the dot)
        float xq0 = 0.f, xq1 = 0.f, xq2 = 0.f, xq3 = 0.f;
        if (tid < 128) {
            const float* xr = g_xg + (size_t)t * (BB * G4) + (size_t)b_r * G4 + j_r;
            xq0 = __ldg(xr);
            xq1 = __ldg(xr + HH);
            xq2 = __ldg(xr + 2 * HH);
            xq3 = __ldg(xr + 3 * HH);
        }
        __syncthreads();

        // ---- dot: 16 b x 1 col x 64 k per thread, w in registers ----
        const float4* hb = hs4f + kc * 17;
#pragma unroll
        for (int bq = 0; bq < 4; bq++) {
            const int b0 = bh * 16 + bq * 4;
            u64 a0 = 0ull, a1 = 0ull, a2 = 0ull, a3 = 0ull;
            const float4* r0p = hb + (size_t)b0 * 136;
            const float4* r1p = r0p + 136;
            const float4* r2p = r1p + 136;
            const float4* r3p = r2p + 136;
#pragma unroll
            for (int m4 = 0; m4 < 16; m4++) {
                ulonglong2 h0v = ((const ulonglong2*)r0p)[m4];
                ulonglong2 h1v = ((const ulonglong2*)r1p)[m4];
                ulonglong2 h2v = ((const ulonglong2*)r2p)[m4];
                ulonglong2 h3v = ((const ulonglong2*)r3p)[m4];
                a0 = fma2(h0v.x, wreg[2 * m4], a0); a0 = fma2(h0v.y, wreg[2 * m4 + 1], a0);
                a1 = fma2(h1v.x, wreg[2 * m4], a1); a1 = fma2(h1v.y, wreg[2 * m4 + 1], a1);
                a2 = fma2(h2v.x, wreg[2 * m4], a2); a2 = fma2(h2v.y, wreg[2 * m4 + 1], a2);
                a3 = fma2(h3v.x, wreg[2 * m4], a3); a3 = fma2(h3v.y, wreg[2 * m4 + 1], a3);
            }
            part[(size_t)(b0 + 0) * 160 + c * 10 + kc] = a0;
            part[(size_t)(b0 + 1) * 160 + c * 10 + kc] = a1;
            part[(size_t)(b0 + 2) * 160 + c * 10 + kc] = a2;
            part[(size_t)(b0 + 3) * 160 + c * 10 + kc] = a3;
        }
        __syncthreads();

        // ---- reduce + activations + h broadcast (tid < 128) ----
        if (tid < 128) {
            float z[4];
#pragma unroll
            for (int g = 0; g < 4; g++) {
                const u64* row = part + (size_t)b_r * 160 + (g * 4 + jj_r) * 10;
                ulonglong2 q0 = ((const ulonglong2*)row)[0];
                ulonglong2 q1 = ((const ulonglong2*)row)[1];
                ulonglong2 q2 = ((const ulonglong2*)row)[2];
                ulonglong2 q3 = ((const ulonglong2*)row)[3];
                u64 s = add2(add2(q0.x, q0.y), add2(q1.x, q1.y));
                s = add2(s, add2(add2(q2.x, q2.y), add2(q3.x, q3.y)));
                float2 uv = unpack2(s);
                z[g] = uv.x + uv.y;
            }
            float ig = fsig(z[0] + xq0);
            float fg = fsig(z[1] + xq1);
            float gg = ftanh(z[2] + xq2);
            float og = fsig(z[3] + xq3);
            creg = fg * creg + ig * gg;
            float hnew = og * ftanh(creg);
            g_hbuf[(t + 1) & 1][b_r * HH + j_r] = hnew;
            ys[(size_t)b_r * (TT * HH) + (size_t)t * HH + j_r] = hnew;
            if (t == TT - 1) {
                outc[b_r * HH + j_r] = creg;
                outh[b_r * HH + j_r] = hnew;
            }
        }

        // ---- grid barrier (tid0-only release/acquire) ----
        __syncthreads();
        if (tid == 0) {
            int* barp = &g_bar[t];
            asm volatile("red.release.gpu.global.add.s32 [%0], 1;"
                         :: "l"(barp) : "memory");
            int v;
            do {
                asm volatile("ld.acquire.gpu.global.s32 %0, [%1];"
                             : "=r"(v) : "l"(barp) : "memory");
            } while (v < NCTA);
        }
        __syncthreads();
    }
}

// ---------------- launcher ----------------
extern "C" void kernel_launch(void* const* d_in, const int* in_sizes, int n_in,
                              void* d_out, int out_size)
{
    const float* x    = (const float*)d_in[0];
    const float* c0   = (const float*)d_in[1];
    const float* h0   = (const float*)d_in[2];
    const float* Wi   = (const float*)d_in[3];
    const float* Wh   = (const float*)d_in[4];
    const float* bias = (const float*)d_in[5];
    float* out = (float*)d_out;

    cudaFuncSetAttribute(lstm_rec, cudaFuncAttributeMaxDynamicSharedMemorySize,
                         SMEM_REC_BYTES);

    gemm_xwi<<<dim3(G4 / 128, (BB * TT) / 128), 256>>>(x, Wi, bias);
    lstm_rec<<<NCTA, 256, SMEM_REC_BYTES>>>(Wh, c0, h0, out);
}

// round 7
// speedup vs baseline: 1.0927x; 1.0927x over previous
#include <cuda_runtime.h>
#include <cuda_bf16.h>
#include <math.h>

#define BB 32
#define TT 2048
#define FF 512
#define HH 512
#define G4 (4*HH)
#define NCTA 128

typedef unsigned long long u64;

// ---------------- scratch ----------------
__device__ float g_xg[(size_t)TT * BB * G4];   // [T][B][4H]
__device__ float g_hbuf[2][BB * HH];           // ping-pong h
__device__ int g_bar[TT];

// ---------------- packed f32x2 + fast-math helpers ----------------
__device__ __forceinline__ u64 f2dup(float v) {
    u64 r; asm("mov.b64 %0, {%1, %1};" : "=l"(r) : "f"(v)); return r;
}
__device__ __forceinline__ u64 fma2(u64 a, u64 b, u64 c) {
    u64 d; asm("fma.rn.f32x2 %0, %1, %2, %3;" : "=l"(d) : "l"(a), "l"(b), "l"(c)); return d;
}
__device__ __forceinline__ float2 unpack2(u64 v) {
    float2 r; asm("mov.b64 {%0, %1}, %2;" : "=f"(r.x), "=f"(r.y) : "l"(v)); return r;
}
__device__ __forceinline__ float fex2(float x) {
    float r; asm("ex2.approx.f32 %0, %1;" : "=f"(r) : "f"(x)); return r;
}
__device__ __forceinline__ float frcp(float x) {
    float r; asm("rcp.approx.f32 %0, %1;" : "=f"(r) : "f"(x)); return r;
}
#define LOG2E 1.4426950408889634f
__device__ __forceinline__ float fsig(float x) { return frcp(1.f + fex2(-LOG2E * x)); }
__device__ __forceinline__ float ftanh(float x) { return 2.f * frcp(1.f + fex2(-2.f * LOG2E * x)) - 1.f; }

// k4 swizzle: bijection on 0..127; makes consecutive-k4 stores AND
// (kt-lane, fixed i) loads both bank-conflict-free.
__device__ __forceinline__ int SWZ(int k4) {
    return (((k4 & 7) << 4) | (k4 >> 3)) ^ (k4 & 7);
}

// ---------------- GEMM: Xg = x @ Wi + bias ----------------
// A staged as plain f32 (dup to f32x2 in registers) -> crossbar balanced w/ fma.
__global__ __launch_bounds__(256) void gemm_xwi(
    const float* __restrict__ x, const float* __restrict__ Wi,
    const float* __restrict__ bias)
{
    __shared__ float asd[2][8][132];
    __shared__ float bsd[2][8][128];

    const int tid = threadIdx.x;
    if (blockIdx.y == 0 && blockIdx.x < 8) {
        g_bar[blockIdx.x * 256 + tid] = 0;   // replay-safe barrier re-init
    }

    const int tx = tid & 15;
    const int ty = tid >> 4;
    const int row0 = blockIdx.y * 128;
    const int col0 = blockIdx.x * 128;

    const int ar = tid >> 1, ac = tid & 1;
    const int br = tid >> 5, bc = tid & 31;

    const float* aptr = x + (size_t)(row0 + ar) * FF + ac * 4;
    const float* bptr = Wi + (size_t)br * G4 + col0 + bc * 4;

    float4 av = *(const float4*)aptr;
    float4 bv = *(const float4*)bptr;

    u64 acc[8][4];
#pragma unroll
    for (int i = 0; i < 8; i++)
#pragma unroll
        for (int j = 0; j < 4; j++) acc[i][j] = 0ull;

    int p = 0;
    for (int s = 0; s < 64; s++) {
        asd[p][ac * 4 + 0][ar] = av.x;
        asd[p][ac * 4 + 1][ar] = av.y;
        asd[p][ac * 4 + 2][ar] = av.z;
        asd[p][ac * 4 + 3][ar] = av.w;
        *(float4*)&bsd[p][br][bc * 4] = bv;
        __syncthreads();
        if (s < 63) {
            av = *(const float4*)(aptr + (s + 1) * 8);
            bv = *(const float4*)(bptr + (size_t)(s + 1) * 8 * G4);
        }
#pragma unroll
        for (int kk = 0; kk < 8; kk++) {
            float4 a0 = *(const float4*)&asd[p][kk][ty * 8];
            float4 a1 = *(const float4*)&asd[p][kk][ty * 8 + 4];
            const ulonglong2* bp2 = (const ulonglong2*)&bsd[p][kk][tx * 8];
            ulonglong2 r0 = bp2[0], r1 = bp2[1];
            u64 aa[8];
            aa[0] = f2dup(a0.x); aa[1] = f2dup(a0.y);
            aa[2] = f2dup(a0.z); aa[3] = f2dup(a0.w);
            aa[4] = f2dup(a1.x); aa[5] = f2dup(a1.y);
            aa[6] = f2dup(a1.z); aa[7] = f2dup(a1.w);
            u64 bb2[4] = {r0.x, r0.y, r1.x, r1.y};
#pragma unroll
            for (int i = 0; i < 8; i++)
#pragma unroll
                for (int j = 0; j < 4; j++)
                    acc[i][j] = fma2(aa[i], bb2[j], acc[i][j]);
        }
        __syncthreads();
        p ^= 1;
    }

    const int cbase = col0 + tx * 8;
    float4 bia0 = *(const float4*)(bias + cbase);
    float4 bia1 = *(const float4*)(bias + cbase + 4);
#pragma unroll
    for (int i = 0; i < 8; i++) {
        int r = row0 + ty * 8 + i;
        int bidx = r >> 11;
        int t = r & (TT - 1);
        float* dst = g_xg + (size_t)t * (BB * G4) + (size_t)bidx * G4 + cbase;
        float2 p0 = unpack2(acc[i][0]);
        float2 p1 = unpack2(acc[i][1]);
        float2 p2 = unpack2(acc[i][2]);
        float2 p3 = unpack2(acc[i][3]);
        float4 v0, v1;
        v0.x = p0.x + bia0.x; v0.y = p0.y + bia0.y;
        v0.z = p1.x + bia0.z; v0.w = p1.y + bia0.w;
        v1.x = p2.x + bia1.x; v1.y = p2.y + bia1.y;
        v1.z = p3.x + bia1.z; v1.w = p3.y + bia1.w;
        *(float4*)(dst) = v0;
        *(float4*)(dst + 4) = v1;
    }
}

// ---------------- persistent recurrent kernel ----------------
// 128 CTAs x 256 threads; CTA owns 16 gate-cols (4 j x 4 gates), all 32 b.
// Thread tile: C=8 cols x B=4 b x K=32 k.  lane = (kt = lane&15, ct = lane>>4),
// warp = bt.  h and Wh both stored k4-swizzled (SWZ) -> conflict-free.
// Partials collapsed to f32 before store (u64 halves are k-parities).
#define HS_F4    (32 * 132)                  // 67584 B
#define W_F4     (16 * 132)                  //  33792 B
#define PART_F   (512 * 20)                  //  40960 B
#define SMEM_REC_BYTES (HS_F4 * 16 + W_F4 * 16 + PART_F * 4)

__global__ __launch_bounds__(256, 1) void lstm_rec(
    const float* __restrict__ Wh,
    const float* __restrict__ c0, const float* __restrict__ h0,
    float* __restrict__ out)
{
    extern __shared__ char smraw[];
    float4* hs4  = (float4*)smraw;                           // [32][132]
    float4* wsm4 = (float4*)(smraw + HS_F4 * 16);            // [16][132]
    float*  part = (float*)(smraw + HS_F4 * 16 + W_F4 * 16); // [512][20]

    const int tid = threadIdx.x;
    const int cta = blockIdx.x;
    const int j0 = cta * 4;

    // Wh slice -> SMEM (swizzled): col c = gate*4 + jj
    {
        float* ws = (float*)wsm4;
        for (int s = tid; s < 8192; s += 256) {
            int kk = s & 3, k4v = (s >> 2) & 127, c = s >> 9;
            int gate = c >> 2, jj = c & 3;
            ws[(c * 132 + SWZ(k4v)) * 4 + kk] =
                Wh[(size_t)(k4v * 4 + kk) * G4 + gate * HH + j0 + jj];
        }
    }

    // dot mapping
    const int lane = tid & 31;
    const int kt = lane & 15;
    const int ct = lane >> 4;
    const int bt = tid >> 5;
    const int c0i = ct * 8;
    const int b0i = bt * 4;

    // reducer mapping (tid < 128): (b, jj)
    const int b_r = tid >> 2;
    const int jj_r = tid & 3;
    const int j_r = j0 + jj_r;

    float creg = 0.f;
    if (tid < 128) creg = c0[b_r * HH + j_r];

    float* outc = out;
    float* outh = out + BB * HH;
    float* ys   = out + 2 * BB * HH;

    for (int t = 0; t < TT; t++) {
        // ---- stage h: coalesced gmem read, swizzled conflict-free smem store ----
        const float4* hsrc = (t == 0) ? (const float4*)h0 : (const float4*)g_hbuf[t & 1];
#pragma unroll
        for (int m = 0; m < 16; m++) {
            int f4 = tid + m * 256;          // b*128 + k4
            int bb = f4 >> 7;
            int k4 = f4 & 127;
            hs4[bb * 132 + SWZ(k4)] = __ldcv(hsrc + f4);
        }
        // xg prefetch (latency hides under the dot)
        float xq0 = 0.f, xq1 = 0.f, xq2 = 0.f, xq3 = 0.f;
        if (tid < 128) {
            const float* xr = g_xg + (size_t)t * (BB * G4) + (size_t)b_r * G4 + j_r;
            xq0 = __ldg(xr);
            xq1 = __ldg(xr + HH);
            xq2 = __ldg(xr + 2 * HH);
            xq3 = __ldg(xr + 3 * HH);
        }
        __syncthreads();

        // ---- dot: 8c x 4b x 32k per thread ----
        u64 acc[8][4];
#pragma unroll
        for (int i = 0; i < 8; i++)
#pragma unroll
            for (int j = 0; j < 4; j++) acc[i][j] = 0ull;

#pragma unroll
        for (int i = 0; i < 8; i++) {
            // k4 = kt*8 + i  ->  SWZ = i*16 + (kt^i)
            const int s = i * 16 + (kt ^ i);
            ulonglong2 hv[4];
#pragma unroll
            for (int b = 0; b < 4; b++)
                hv[b] = *(const ulonglong2*)(hs4 + (b0i + b) * 132 + s);
            ulonglong2 wv[8];
#pragma unroll
            for (int c = 0; c < 8; c++)
                wv[c] = *(const ulonglong2*)(wsm4 + (c0i + c) * 132 + s);
#pragma unroll
            for (int c = 0; c < 8; c++)
#pragma unroll
                for (int b = 0; b < 4; b++) {
                    acc[c][b] = fma2(hv[b].x, wv[c].x, acc[c][b]);
                    acc[c][b] = fma2(hv[b].y, wv[c].y, acc[c][b]);
                }
        }

        // collapse u64 -> f32 and store partials: part[(c*32+b)*20 + kt]
#pragma unroll
        for (int c = 0; c < 8; c++)
#pragma unroll
            for (int b = 0; b < 4; b++) {
                float2 uv = unpack2(acc[c][b]);
                part[((c0i + c) * 32 + (b0i + b)) * 20 + kt] = uv.x + uv.y;
            }
        __syncthreads();

        // ---- reduce 16 kt + activations + h broadcast (tid < 128) ----
        if (tid < 128) {
            float z[4];
#pragma unroll
            for (int g = 0; g < 4; g++) {
                const float* row = part + ((g * 4 + jj_r) * 32 + b_r) * 20;
                float4 q0 = *(const float4*)(row);
                float4 q1 = *(const float4*)(row + 4);
                float4 q2 = *(const float4*)(row + 8);
                float4 q3 = *(const float4*)(row + 12);
                z[g] = ((q0.x + q0.y) + (q0.z + q0.w))
                     + ((q1.x + q1.y) + (q1.z + q1.w))
                     + ((q2.x + q2.y) + (q2.z + q2.w))
                     + ((q3.x + q3.y) + (q3.z + q3.w));
            }
            float ig = fsig(z[0] + xq0);
            float fg = fsig(z[1] + xq1);
            float gg = ftanh(z[2] + xq2);
            float og = fsig(z[3] + xq3);
            creg = fg * creg + ig * gg;
            float hnew = og * ftanh(creg);
            g_hbuf[(t + 1) & 1][b_r * HH + j_r] = hnew;
            ys[(size_t)b_r * (TT * HH) + (size_t)t * HH + j_r] = hnew;
            if (t == TT - 1) {
                outc[b_r * HH + j_r] = creg;
                outh[b_r * HH + j_r] = hnew;
            }
        }

        // ---- grid barrier (tid0-only release/acquire) ----
        __syncthreads();
        if (tid == 0) {
            int* barp = &g_bar[t];
            asm volatile("red.release.gpu.global.add.s32 [%0], 1;"
                         :: "l"(barp) : "memory");
            int v;
            do {
                asm volatile("ld.acquire.gpu.global.s32 %0, [%1];"
                             : "=r"(v) : "l"(barp) : "memory");
            } while (v < NCTA);
        }
        __syncthreads();
    }
}

// ---------------- launcher ----------------
extern "C" void kernel_launch(void* const* d_in, const int* in_sizes, int n_in,
                              void* d_out, int out_size)
{
    const float* x    = (const float*)d_in[0];
    const float* c0   = (const float*)d_in[1];
    const float* h0   = (const float*)d_in[2];
    const float* Wi   = (const float*)d_in[3];
    const float* Wh   = (const float*)d_in[4];
    const float* bias = (const float*)d_in[5];
    float* out = (float*)d_out;

    cudaFuncSetAttribute(lstm_rec, cudaFuncAttributeMaxDynamicSharedMemorySize,
                         SMEM_REC_BYTES);

    gemm_xwi<<<dim3(G4 / 128, (BB * TT) / 128), 256>>>(x, Wi, bias);
    lstm_rec<<<NCTA, 256, SMEM_REC_BYTES>>>(Wh, c0, h0, out);
}

// round 8
// speedup vs baseline: 1.3597x; 1.2444x over previous
#include <cuda_runtime.h>
#include <cuda_bf16.h>
#include <math.h>

#define BB 32
#define TT 2048
#define FF 512
#define HH 512
#define G4 (4*HH)
#define NGRP 4
#define GCTA 32            // CTAs per group
#define NCTA (NGRP*GCTA)   // 128

typedef unsigned long long u64;

// ---------------- scratch ----------------
__device__ float g_xg[(size_t)TT * BB * G4];   // [T][B][4H]
__device__ float g_hbuf[2][BB * HH];           // ping-pong h
__device__ int g_bar[NGRP * TT];

// ---------------- packed f32x2 + fast-math helpers ----------------
__device__ __forceinline__ u64 f2dup(float v) {
    u64 r; asm("mov.b64 %0, {%1, %1};" : "=l"(r) : "f"(v)); return r;
}
__device__ __forceinline__ u64 fma2(u64 a, u64 b, u64 c) {
    u64 d; asm("fma.rn.f32x2 %0, %1, %2, %3;" : "=l"(d) : "l"(a), "l"(b), "l"(c)); return d;
}
__device__ __forceinline__ float2 unpack2(u64 v) {
    float2 r; asm("mov.b64 {%0, %1}, %2;" : "=f"(r.x), "=f"(r.y) : "l"(v)); return r;
}
__device__ __forceinline__ float fex2(float x) {
    float r; asm("ex2.approx.f32 %0, %1;" : "=f"(r) : "f"(x)); return r;
}
__device__ __forceinline__ float frcp(float x) {
    float r; asm("rcp.approx.f32 %0, %1;" : "=f"(r) : "f"(x)); return r;
}
#define LOG2E 1.4426950408889634f
__device__ __forceinline__ float fsig(float x) { return frcp(1.f + fex2(-LOG2E * x)); }
__device__ __forceinline__ float ftanh(float x) { return 2.f * frcp(1.f + fex2(-2.f * LOG2E * x)) - 1.f; }

// k4 swizzle: bijection on 0..127; conflict-free for staged stores and dot loads
__device__ __forceinline__ int SWZ(int k4) {
    return (((k4 & 7) << 4) | (k4 >> 3)) ^ (k4 & 7);
}

// ---------------- GEMM: Xg = x @ Wi + bias ----------------
__global__ __launch_bounds__(256) void gemm_xwi(
    const float* __restrict__ x, const float* __restrict__ Wi,
    const float* __restrict__ bias)
{
    __shared__ float asd[2][8][132];
    __shared__ float bsd[2][8][128];

    const int tid = threadIdx.x;
    if (blockIdx.y == 0) {   // zero 4*2048 = 8192 barrier counters (replay safety)
        g_bar[blockIdx.x * 512 + tid] = 0;
        g_bar[blockIdx.x * 512 + 256 + tid] = 0;
    }

    const int tx = tid & 15;
    const int ty = tid >> 4;
    const int row0 = blockIdx.y * 128;
    const int col0 = blockIdx.x * 128;

    const int ar = tid >> 1, ac = tid & 1;
    const int br = tid >> 5, bc = tid & 31;

    const float* aptr = x + (size_t)(row0 + ar) * FF + ac * 4;
    const float* bptr = Wi + (size_t)br * G4 + col0 + bc * 4;

    float4 av = *(const float4*)aptr;
    float4 bv = *(const float4*)bptr;

    u64 acc[8][4];
#pragma unroll
    for (int i = 0; i < 8; i++)
#pragma unroll
        for (int j = 0; j < 4; j++) acc[i][j] = 0ull;

    int p = 0;
    for (int s = 0; s < 64; s++) {
        asd[p][ac * 4 + 0][ar] = av.x;
        asd[p][ac * 4 + 1][ar] = av.y;
        asd[p][ac * 4 + 2][ar] = av.z;
        asd[p][ac * 4 + 3][ar] = av.w;
        *(float4*)&bsd[p][br][bc * 4] = bv;
        __syncthreads();
        if (s < 63) {
            av = *(const float4*)(aptr + (s + 1) * 8);
            bv = *(const float4*)(bptr + (size_t)(s + 1) * 8 * G4);
        }
#pragma unroll
        for (int kk = 0; kk < 8; kk++) {
            float4 a0 = *(const float4*)&asd[p][kk][ty * 8];
            float4 a1 = *(const float4*)&asd[p][kk][ty * 8 + 4];
            const ulonglong2* bp2 = (const ulonglong2*)&bsd[p][kk][tx * 8];
            ulonglong2 r0 = bp2[0], r1 = bp2[1];
            u64 aa[8];
            aa[0] = f2dup(a0.x); aa[1] = f2dup(a0.y);
            aa[2] = f2dup(a0.z); aa[3] = f2dup(a0.w);
            aa[4] = f2dup(a1.x); aa[5] = f2dup(a1.y);
            aa[6] = f2dup(a1.z); aa[7] = f2dup(a1.w);
            u64 bb2[4] = {r0.x, r0.y, r1.x, r1.y};
#pragma unroll
            for (int i = 0; i < 8; i++)
#pragma unroll
                for (int j = 0; j < 4; j++)
                    acc[i][j] = fma2(aa[i], bb2[j], acc[i][j]);
        }
        __syncthreads();
        p ^= 1;
    }

    const int cbase = col0 + tx * 8;
    float4 bia0 = *(const float4*)(bias + cbase);
    float4 bia1 = *(const float4*)(bias + cbase + 4);
#pragma unroll
    for (int i = 0; i < 8; i++) {
        int r = row0 + ty * 8 + i;
        int bidx = r >> 11;
        int t = r & (TT - 1);
        float* dst = g_xg + (size_t)t * (BB * G4) + (size_t)bidx * G4 + cbase;
        float2 p0 = unpack2(acc[i][0]);
        float2 p1 = unpack2(acc[i][1]);
        float2 p2 = unpack2(acc[i][2]);
        float2 p3 = unpack2(acc[i][3]);
        float4 v0, v1;
        v0.x = p0.x + bia0.x; v0.y = p0.y + bia0.y;
        v0.z = p1.x + bia0.z; v0.w = p1.y + bia0.w;
        v1.x = p2.x + bia1.x; v1.y = p2.y + bia1.y;
        v1.z = p3.x + bia1.z; v1.w = p3.y + bia1.w;
        *(float4*)(dst) = v0;
        *(float4*)(dst + 4) = v1;
    }
}

// ---------------- persistent recurrent kernel: 4 independent batch groups ----
// Group (cta>>5) owns 8 batches; CTA (cta&31) owns 16 j's (64 gate-cols).
// Thread tile C=8 cols x B=4 b x K=32 k, kt = tid&15, ct = (tid>>4)&7, bt = tid>>7.
// Per-group barrier (fan-in 32).  part rows transposed (b*64+c) -> reduce
// jj-lane row stride 5 f4, coprime 8 -> conflict-free.
#define HS_F4    (8 * 132)                   //  16896 B
#define W_F4     (64 * 132)                  // 135168 B
#define PART_F   (512 * 20)                  //  40960 B
#define SMEM_REC_BYTES (HS_F4 * 16 + W_F4 * 16 + PART_F * 4)

__global__ __launch_bounds__(256, 1) void lstm_rec(
    const float* __restrict__ Wh,
    const float* __restrict__ c0, const float* __restrict__ h0,
    float* __restrict__ out)
{
    extern __shared__ char smraw[];
    float4* hs4  = (float4*)smraw;                           // [8][132]
    float4* wsm4 = (float4*)(smraw + HS_F4 * 16);            // [64][132]
    float*  part = (float*)(smraw + HS_F4 * 16 + W_F4 * 16); // [512][20]

    const int tid = threadIdx.x;
    const int cta = blockIdx.x;
    const int grp = cta >> 5;
    const int cgc = cta & 31;
    const int j0  = cgc * 16;       // first j owned by this CTA
    const int bG0 = grp * 8;        // first batch of this group

    // Wh slice -> SMEM (swizzled): 64 cols x 512 k, col c = gate*16 + jj
    {
        float* ws = (float*)wsm4;
        for (int s = tid; s < 32768; s += 256) {
            int kk = s & 3, k4v = (s >> 2) & 127, c = s >> 9;
            int gate = c >> 4, jj = c & 15;
            ws[(c * 132 + SWZ(k4v)) * 4 + kk] =
                Wh[(size_t)(k4v * 4 + kk) * G4 + gate * HH + j0 + jj];
        }
    }

    // dot mapping
    const int kt = tid & 15;
    const int ct = (tid >> 4) & 7;
    const int bt = tid >> 7;
    const int c0i = ct * 8;
    const int b0i = bt * 4;

    // reducer mapping (tid < 128): (b_r in 8, jj_r in 16)
    const int b_r  = tid >> 4;
    const int jj_r = tid & 15;
    const int bGr  = bG0 + b_r;
    const int jGr  = j0 + jj_r;

    float creg = 0.f;
    if (tid < 128) creg = c0[bGr * HH + jGr];

    float* outc = out;
    float* outh = out + BB * HH;
    float* ys   = out + 2 * BB * HH;

    for (int t = 0; t < TT; t++) {
        // ---- stage this group's h (8 b x 512): 4 f4 loads/thread ----
        const float4* hsrc = ((t == 0) ? (const float4*)h0 : (const float4*)g_hbuf[t & 1])
                             + bG0 * 128;
#pragma unroll
        for (int m = 0; m < 4; m++) {
            int f4 = tid + m * 256;          // bb*128 + k4, bb in 0..7
            int bb = f4 >> 7;
            int k4 = f4 & 127;
            hs4[bb * 132 + SWZ(k4)] = __ldcv(hsrc + f4);
        }
        // xg prefetch (hides under the dot)
        float xq0 = 0.f, xq1 = 0.f, xq2 = 0.f, xq3 = 0.f;
        if (tid < 128) {
            const float* xr = g_xg + (size_t)t * (BB * G4) + (size_t)bGr * G4 + jGr;
            xq0 = __ldg(xr);
            xq1 = __ldg(xr + HH);
            xq2 = __ldg(xr + 2 * HH);
            xq3 = __ldg(xr + 3 * HH);
        }
        __syncthreads();

        // ---- dot: 8c x 4b x 32k per thread ----
        u64 acc[8][4];
#pragma unroll
        for (int i = 0; i < 8; i++)
#pragma unroll
            for (int j = 0; j < 4; j++) acc[i][j] = 0ull;

#pragma unroll
        for (int i = 0; i < 8; i++) {
            const int s = i * 16 + (kt ^ i);   // SWZ(kt*8+i)
            ulonglong2 hv[4];
#pragma unroll
            for (int b = 0; b < 4; b++)
                hv[b] = *(const ulonglong2*)(hs4 + (b0i + b) * 132 + s);
            ulonglong2 wv[8];
#pragma unroll
            for (int c = 0; c < 8; c++)
                wv[c] = *(const ulonglong2*)(wsm4 + (c0i + c) * 132 + s);
#pragma unroll
            for (int c = 0; c < 8; c++)
#pragma unroll
                for (int b = 0; b < 4; b++) {
                    acc[c][b] = fma2(hv[b].x, wv[c].x, acc[c][b]);
                    acc[c][b] = fma2(hv[b].y, wv[c].y, acc[c][b]);
                }
        }

        // collapse u64 -> f32; part row = b*64 + c
#pragma unroll
        for (int c = 0; c < 8; c++)
#pragma unroll
            for (int b = 0; b < 4; b++) {
                float2 uv = unpack2(acc[c][b]);
                part[((b0i + b) * 64 + (c0i + c)) * 20 + kt] = uv.x + uv.y;
            }
        __syncthreads();

        // ---- reduce 16 kt + activations + h broadcast (tid < 128) ----
        if (tid < 128) {
            float z[4];
#pragma unroll
            for (int g = 0; g < 4; g++) {
                const float* row = part + (b_r * 64 + g * 16 + jj_r) * 20;
                float4 q0 = *(const float4*)(row);
                float4 q1 = *(const float4*)(row + 4);
                float4 q2 = *(const float4*)(row + 8);
                float4 q3 = *(const float4*)(row + 12);
                z[g] = ((q0.x + q0.y) + (q0.z + q0.w))
                     + ((q1.x + q1.y) + (q1.z + q1.w))
                     + ((q2.x + q2.y) + (q2.z + q2.w))
                     + ((q3.x + q3.y) + (q3.z + q3.w));
            }
            float ig = fsig(z[0] + xq0);
            float fg = fsig(z[1] + xq1);
            float gg = ftanh(z[2] + xq2);
            float og = fsig(z[3] + xq3);
            creg = fg * creg + ig * gg;
            float hnew = og * ftanh(creg);
            g_hbuf[(t + 1) & 1][bGr * HH + jGr] = hnew;
            ys[(size_t)bGr * (TT * HH) + (size_t)t * HH + jGr] = hnew;
            if (t == TT - 1) {
                outc[bGr * HH + jGr] = creg;
                outh[bGr * HH + jGr] = hnew;
            }
        }

        // ---- per-group barrier (fan-in 32, tid0 release/acquire) ----
        __syncthreads();
        if (tid == 0) {
            int* barp = &g_bar[grp * TT + t];
            asm volatile("red.release.gpu.global.add.s32 [%0], 1;"
                         :: "l"(barp) : "memory");
            int v;
            do {
                asm volatile("ld.acquire.gpu.global.s32 %0, [%1];"
                             : "=r"(v) : "l"(barp) : "memory");
            } while (v < GCTA);
        }
        __syncthreads();
    }
}

// ---------------- launcher ----------------
extern "C" void kernel_launch(void* const* d_in, const int* in_sizes, int n_in,
                              void* d_out, int out_size)
{
    const float* x    = (const float*)d_in[0];
    const float* c0   = (const float*)d_in[1];
    const float* h0   = (const float*)d_in[2];
    const float* Wi   = (const float*)d_in[3];
    const float* Wh   = (const float*)d_in[4];
    const float* bias = (const float*)d_in[5];
    float* out = (float*)d_out;

    cudaFuncSetAttribute(lstm_rec, cudaFuncAttributeMaxDynamicSharedMemorySize,
                         SMEM_REC_BYTES);

    gemm_xwi<<<dim3(G4 / 128, (BB * TT) / 128), 256>>>(x, Wi, bias);
    lstm_rec<<<NCTA, 256, SMEM_REC_BYTES>>>(Wh, c0, h0, out);
}